// round 7
// baseline (speedup 1.0000x reference)
#include <cuda_runtime.h>
#include <math.h>

#define B_ 8
#define N_ 65536
#define M_ 8
#define GRID 148
#define THREADS 512
#define TOTAL4 (B_ * N_ * 4)           // 2,097,152 float4 elements
#define CHUNK4 14172                    // float4s per block (mult of 4); 148*14172 >= TOTAL4
#define CHUNK_CELLS (CHUNK4 / 4)        // 3543 cells
#define SMEM_BYTES (CHUNK4 * 16)        // 226752 B dynamic smem

// Scratch (no cudaMalloc allowed)
__device__ float4 g_sums[GRID][2][4];   // [blk][slot(b0,b0+1)][quarter]
__device__ unsigned g_bar = 0;
__device__ unsigned g_done = 0;

// ---------------------------------------------------------------------------
// Compile-time Cayley sign for Cl(3,0,1), replicating the reference loop.
// ---------------------------------------------------------------------------
__host__ __device__ constexpr int cpop4(unsigned v) {
    return (int)((v & 1u) + ((v >> 1) & 1u) + ((v >> 2) & 1u) + ((v >> 3) & 1u));
}
__host__ __device__ constexpr float csign(int i, int j) {
    float s = 1.0f;
    for (int b = 0; b < 4; b++) {
        if ((j >> b) & 1) {
            if (cpop4((unsigned)(i >> (b + 1))) & 1) s = -s;
            if ((i >> b) & 1) {
                if (b == 0) s = 0.0f;  // metric[0] = 0
            }
        }
    }
    return s;
}

// smem transpose swizzle: quarter q of local cell c -> f4 slot
__device__ __forceinline__ int swz(int c, int q) {
    return (c << 2) + (q ^ ((c ^ (c >> 2)) & 3));
}

// ---------------------------------------------------------------------------
// Threefry-2x32 (JAX partitionable scheme: counter (0, e), bits = o0^o1)
// ---------------------------------------------------------------------------
__device__ __forceinline__ unsigned tf_rotl(unsigned v, int d) {
    return (v << d) | (v >> (32 - d));
}

__device__ void threefry2x32(unsigned k0, unsigned k1,
                             unsigned c0, unsigned c1,
                             unsigned& o0, unsigned& o1) {
    unsigned ks0 = k0, ks1 = k1, ks2 = k0 ^ k1 ^ 0x1BD11BDAu;
    unsigned x0 = c0 + ks0;
    unsigned x1 = c1 + ks1;
    const int r0[4] = {13, 15, 26, 6};
    const int r1[4] = {17, 29, 16, 24};
#define TF_BLOCK(R)                                            \
    {                                                          \
        _Pragma("unroll")                                      \
        for (int q = 0; q < 4; q++) {                          \
            x0 += x1;                                          \
            x1 = tf_rotl(x1, (R)[q]);                          \
            x1 ^= x0;                                          \
        }                                                      \
    }
    TF_BLOCK(r0); x0 += ks1; x1 += ks2 + 1u;
    TF_BLOCK(r1); x0 += ks2; x1 += ks0 + 2u;
    TF_BLOCK(r0); x0 += ks0; x1 += ks1 + 3u;
    TF_BLOCK(r1); x0 += ks1; x1 += ks2 + 4u;
    TF_BLOCK(r0); x0 += ks2; x1 += ks0 + 5u;
#undef TF_BLOCK
    o0 = x0; o1 = x1;
}

// ---------------------------------------------------------------------------
// One persistent kernel: stream-in + reduce | grid barrier | score | apply +
// stream-out. 148 blocks, 1 block/SM (smem-bound) -> all co-resident.
// ---------------------------------------------------------------------------
__global__ void __launch_bounds__(THREADS, 1)
gss_fused_kernel(const float* __restrict__ state,
                 const float* __restrict__ ctrl,
                 const float* __restrict__ rule_mem,
                 const float* __restrict__ templates,
                 const float* __restrict__ W1,
                 const float* __restrict__ b1,
                 const float* __restrict__ W2,
                 const float* __restrict__ b2,
                 const float* __restrict__ Wr,
                 const float* __restrict__ br,
                 const float* __restrict__ log_temp,
                 float* __restrict__ out) {
    extern __shared__ float4 sm4[];      // CHUNK4 float4s (swizzled cell data)

    const int tid  = threadIdx.x;
    const int blk  = blockIdx.x;
    const int lane = tid & 31;
    const int warp = tid >> 5;

    const int start4 = blk * CHUNK4;
    int cnt = TOTAL4 - start4; if (cnt > CHUNK4) cnt = CHUNK4;
    const float4* gsrc = (const float4*)state + start4;
    float4* gdst = (float4*)out + start4;

    const int b0    = start4 >> 18;                 // first batch in chunk
    const int bndry = ((b0 + 1) << 18) - start4;    // local f4 idx of batch flip

    // ---- Phase 1: stream chunk into swizzled smem, accumulate per-batch sums
    float4 acc0 = make_float4(0.f, 0.f, 0.f, 0.f);
    float4 acc1 = make_float4(0.f, 0.f, 0.f, 0.f);
#pragma unroll 4
    for (int L = tid; L < cnt; L += THREADS) {
        float4 v = __ldcs(gsrc + L);
        sm4[swz(L >> 2, L & 3)] = v;
        if (L < bndry) {
            acc0.x += v.x; acc0.y += v.y; acc0.z += v.z; acc0.w += v.w;
        } else {
            acc1.x += v.x; acc1.y += v.y; acc1.z += v.z; acc1.w += v.w;
        }
    }
    // warp reduce preserving quarter class (lane%4); offsets 16/8/4
#pragma unroll
    for (int off = 16; off >= 4; off >>= 1) {
        acc0.x += __shfl_xor_sync(0xffffffffu, acc0.x, off);
        acc0.y += __shfl_xor_sync(0xffffffffu, acc0.y, off);
        acc0.z += __shfl_xor_sync(0xffffffffu, acc0.z, off);
        acc0.w += __shfl_xor_sync(0xffffffffu, acc0.w, off);
        acc1.x += __shfl_xor_sync(0xffffffffu, acc1.x, off);
        acc1.y += __shfl_xor_sync(0xffffffffu, acc1.y, off);
        acc1.z += __shfl_xor_sync(0xffffffffu, acc1.z, off);
        acc1.w += __shfl_xor_sync(0xffffffffu, acc1.w, off);
    }
    __shared__ float4 red[16][2][4];
    if (lane < 4) { red[warp][0][lane] = acc0; red[warp][1][lane] = acc1; }
    __syncthreads();
    if (warp == 0 && lane < 8) {
        int s = lane >> 2, q = lane & 3;
        float4 t = make_float4(0.f, 0.f, 0.f, 0.f);
#pragma unroll
        for (int w = 0; w < 16; w++) {
            float4 r = red[w][s][q];
            t.x += r.x; t.y += r.y; t.z += r.z; t.w += r.w;
        }
        g_sums[blk][s][q] = t;
        __threadfence();                 // release this lane's g_sums write
    }
    __syncthreads();

    // ---- Grid barrier (148 co-resident blocks)
    if (tid == 0) {
        atomicAdd(&g_bar, 1u);
        while (*(volatile unsigned*)&g_bar < (unsigned)GRID) __nanosleep(64);
        __threadfence();                 // acquire
    }
    __syncthreads();

    // ---- Phase 2: redundant per-block scoring pipeline -> combS
    __shared__ float summ[B_][16];
    __shared__ float si_s[B_][12];
    __shared__ float sc_s[B_][8];
    __shared__ float rs_s[B_][16];
    __shared__ float wts_s[B_][8];
    __shared__ float combS[B_][16];

    if (warp < 8) {
        int b = warp;

        if (lane < 16) {
            float s = 0.f;
            const float* gs = (const float*)g_sums;   // [blk][2][16]
            for (int k = 0; k < GRID; k++) {
                int kb0 = (k * CHUNK4) >> 18;
                if (kb0 == b)     s += gs[k * 32 + lane];
                if (kb0 + 1 == b) s += gs[k * 32 + 16 + lane];
            }
            summ[b][lane] = s * (1.0f / N_);
        }
        __syncwarp();

        if (lane < 5) {
            float s = 0.f;
            for (int d = 0; d < 16; d++)
                if (__popc(d) == lane) { float v = summ[b][d]; s += v * v; }
            si_s[b][lane] = sqrtf(s + 1e-12f);
        }
        if (lane >= 5 && lane < 9) si_s[b][lane] = ctrl[b * 4 + (lane - 5)];
        __syncwarp();

        // MLP in registers: lane holds hidden units {lane, lane+32}
        float h0 = b1[lane], h1 = b1[lane + 32];
#pragma unroll
        for (int i = 0; i < 9; i++) {
            float v = si_s[b][i];
            h0 += v * W1[i * 64 + lane];
            h1 += v * W1[i * 64 + lane + 32];
        }
        h0 = fmaxf(h0, 0.f); h1 = fmaxf(h1, 0.f);
        float p[8];
#pragma unroll
        for (int k = 0; k < 8; k++)
            p[k] = h0 * W2[lane * 8 + k] + h1 * W2[(lane + 32) * 8 + k];
#pragma unroll
        for (int off = 16; off >= 1; off >>= 1)
#pragma unroll
            for (int k = 0; k < 8; k++)
                p[k] += __shfl_xor_sync(0xffffffffu, p[k], off);
        if (lane == 0)
#pragma unroll
            for (int k = 0; k < 8; k++) sc_s[b][k] = p[k] + b2[k];

        if (lane < 16) {
            float s = 0.f;
            for (int m = 0; m < M_; m++) s += rule_mem[(b * M_ + m) * 16 + lane];
            rs_s[b][lane] = s * 0.125f;
        }
        __syncwarp();

        if (lane < 8) {
            int e = b * 8 + lane;
            unsigned o0, o1;
            threefry2x32(0u, 42u, 0u, (unsigned)e, o0, o1);
            unsigned bits = o0 ^ o1;
            float u = __uint_as_float((bits >> 9) | 0x3f800000u) - 1.0f;
            const float minv = 1e-6f, maxv = 1.0f - 1e-6f;
            u = fmaxf(minv, u * (maxv - minv) + minv);
            float g = -logf(-logf(u));
            float tau = fminf(fmaxf(expf(log_temp[0]), 0.1f), 5.0f);
            wts_s[b][lane] = (sc_s[b][lane] + g) / tau;
        }
        __syncwarp();

        if (lane == 0) {
            float mx = -1e30f;
            for (int k = 0; k < 8; k++) mx = fmaxf(mx, wts_s[b][k]);
            float s = 0.f;
            for (int k = 0; k < 8; k++) { float e = expf(wts_s[b][k] - mx); wts_s[b][k] = e; s += e; }
            float inv = 1.0f / s;
            for (int k = 0; k < 8; k++) wts_s[b][k] *= inv;
        }
        __syncwarp();

        if (lane < 16) {
            float s = 0.f;
#pragma unroll
            for (int k = 0; k < 8; k++) {
                float t = templates[k * 16 + lane] + br[k * 16 + lane];
#pragma unroll
                for (int d = 0; d < 16; d++)
                    t += rs_s[b][d] * Wr[d * 128 + k * 16 + lane];
                s += wts_s[b][k] * sc_s[b][k] * t;
            }
            combS[b][lane] = s;
        }
    }
    __syncthreads();

    // ---- Phase 3: apply operator to smem-resident cells (in place)
    const int cellStart = blk * CHUNK_CELLS;
    const int cellCnt = cnt >> 2;

    int curb = cellStart >> 16;
    float a[16];
#pragma unroll
    for (int j = 0; j < 16; j++) a[j] = combS[curb][j];

    for (int c = tid; c < cellCnt; c += THREADS) {
        int bb = (cellStart + c) >> 16;
        if (bb != curb) {
            curb = bb;
#pragma unroll
            for (int j = 0; j < 16; j++) a[j] = combS[curb][j];
        }
        float x[16];
#pragma unroll
        for (int q = 0; q < 4; q++) {
            float4 v = sm4[swz(c, q)];
            x[q * 4 + 0] = v.x; x[q * 4 + 1] = v.y;
            x[q * 4 + 2] = v.z; x[q * 4 + 3] = v.w;
        }
        float y[16];
#pragma unroll
        for (int l = 0; l < 16; l++) {
            float s = 0.f;
#pragma unroll
            for (int j = 0; j < 16; j++) {
                const float sgn = csign(j ^ l, j);   // compile-time constant
                if (sgn > 0.5f)       s = fmaf(a[j ^ l],  x[j], s);
                else if (sgn < -0.5f) s = fmaf(-a[j ^ l], x[j], s);
            }
            y[l] = s;
        }
#pragma unroll
        for (int q = 0; q < 4; q++)
            sm4[swz(c, q)] = make_float4(y[q * 4 + 0], y[q * 4 + 1],
                                         y[q * 4 + 2], y[q * 4 + 3]);
    }
    __syncthreads();

    // ---- coalesced stream-out
#pragma unroll 4
    for (int L = tid; L < cnt; L += THREADS)
        __stcs(gdst + L, sm4[swz(L >> 2, L & 3)]);

    // ---- reset barrier counters for next graph replay
    if (tid == 0) {
        if (atomicAdd(&g_done, 1u) == (unsigned)(GRID - 1)) {
            g_bar = 0;
            g_done = 0;
        }
    }
}

extern "C" void kernel_launch(void* const* d_in, const int* in_sizes, int n_in,
                              void* d_out, int out_size) {
    const float* cpu_state   = (const float*)d_in[0];
    const float* ctrl_cursor = (const float*)d_in[1];
    const float* rule_memory = (const float*)d_in[2];
    const float* templates   = (const float*)d_in[3];
    const float* W1          = (const float*)d_in[4];
    const float* b1          = (const float*)d_in[5];
    const float* W2          = (const float*)d_in[6];
    const float* b2          = (const float*)d_in[7];
    const float* Wr          = (const float*)d_in[8];
    const float* br          = (const float*)d_in[9];
    const float* log_temp    = (const float*)d_in[10];
    float* out = (float*)d_out;

    static bool configured = false;
    if (!configured) {
        cudaFuncSetAttribute(gss_fused_kernel,
                             cudaFuncAttributeMaxDynamicSharedMemorySize,
                             SMEM_BYTES);
        configured = true;
    }

    gss_fused_kernel<<<GRID, THREADS, SMEM_BYTES>>>(
        cpu_state, ctrl_cursor, rule_memory, templates,
        W1, b1, W2, b2, Wr, br, log_temp, out);
}